// round 1
// baseline (speedup 1.0000x reference)
#include <cuda_runtime.h>
#include <cstdint>

// Problem constants
#define B   128
#define T   1024
#define H   512
#define G   2048   // 4*H gate columns
#define V   256
#define NBLK 128   // 32 h-unit groups x 4 batch groups
#define NTHR 256
#define BT   32    // batch tile per block
#define GC   64    // gate cols per block (16 h-units x 4 gates)

// Shared memory carve (bytes)
#define WS_BYTES (256*64*8)   // Ws2: [256 k2][64 g] float2   = 131072
#define HS_BYTES (256*32*8)   // Hs2: [256 k2][32 b] float2   =  65536
#define GS_STRIDE 66
#define GS_BYTES (32*GS_STRIDE*4)   // gates staging            =   8448
#define SMEM_BYTES (WS_BYTES + HS_BYTES + GS_BYTES + 128 + 128) // + vbuf + xls = 205312

// Device-global scratch (allocation-free per harness rules)
__device__ float     g_WihT[V*G];              // W_ih^T with biases folded in: [v][g]
__device__ float2    g_hbuf[2][(H/2)*B];       // double-buffered h, k-pair interleaved: [k2][b]
__device__ unsigned  g_bar;

__device__ __forceinline__ void fma2(unsigned long long &d, unsigned long long a, unsigned long long b) {
    asm volatile("fma.rn.f32x2 %0, %1, %2, %0;" : "+l"(d) : "l"(a), "l"(b));
}
__device__ __forceinline__ float2 u2f(unsigned long long v) {
    float2 r; asm("mov.b64 {%0, %1}, %2;" : "=f"(r.x), "=f"(r.y) : "l"(v)); return r;
}
__device__ __forceinline__ float sigf(float x) { return 1.0f / (1.0f + expf(-x)); }

// Per-launch init: reset barrier, zero h0 buffer, build gathered projection table
// projT[v][g] = W_ih[g][v] + b_ih[g] + b_hh[g]
__global__ void init_kernel(const float* __restrict__ W_ih,
                            const float* __restrict__ b_ih,
                            const float* __restrict__ b_hh) {
    int idx = blockIdx.x * blockDim.x + threadIdx.x;
    int stride = gridDim.x * blockDim.x;
    if (idx == 0) g_bar = 0u;
    for (int i = idx; i < V*G; i += stride) {
        int v = i >> 11;           // /G
        int g = i & (G - 1);
        g_WihT[i] = W_ih[g*V + v] + b_ih[g] + b_hh[g];
    }
    for (int i = idx; i < (H/2)*B; i += stride) g_hbuf[0][i] = make_float2(0.f, 0.f);
}

extern __shared__ char smem_raw[];

__global__ __launch_bounds__(NTHR, 1)
void lstm_persistent(const int* __restrict__ x, const int* __restrict__ x_len,
                     const float* __restrict__ W_hh, float* __restrict__ out) {
    float2* Ws2 = (float2*)smem_raw;                       // [256][64] k-pair packed W slice
    float2* Hs2 = (float2*)(smem_raw + WS_BYTES);          // [256][32] k-pair packed h tile
    float*  Gs  = (float*)(smem_raw + WS_BYTES + HS_BYTES);// [32][66] gates
    int*   vbuf = (int*)(Gs + 32*GS_STRIDE);               // [32] token ids this step
    int*   xls  = vbuf + 32;                               // [32] x_len cache

    const int tid  = threadIdx.x;
    const int hug  = blockIdx.x & 31;   // h-unit group
    const int bg   = blockIdx.x >> 5;   // batch group
    const int hu0  = hug * 16;
    const int b0   = bg * BT;
    const int lane = tid & 31;          // gate-col group (2 cols each)
    const int bgrp = tid >> 5;          // batch group within tile (4 rows each)

    // ---- Prologue: load W_hh slice (resident all 1024 steps), x_len cache ----
    for (int i = tid; i < GC*256; i += NTHR) {
        int k2 = i >> 6, c = i & 63;
        int grow = ((c >> 4) << 9) + hu0 + (c & 15);   // gate_type*512 + hu0 + u
        Ws2[k2*64 + c] = *(const float2*)&W_hh[grow*H + 2*k2];
    }
    if (tid < BT) xls[tid] = x_len[b0 + tid];

    // Pointwise mapping (fixed per thread for the whole kernel -> c lives in regs)
    const int u2 = tid >> 5;   // 0..7  (h-unit pair index)
    const int pb = tid & 31;   // batch row
    float2 creg = make_float2(0.f, 0.f);

    for (int t = 0; t < T; ++t) {
        // ---- Fill Hs2 from global h (double-buffered) ----
        {
            const float4* src = (const float4*)(g_hbuf[t & 1]);
            float4* dst = (float4*)Hs2;
            #pragma unroll
            for (int i = tid; i < 4096; i += NTHR) {
                int k2 = i >> 4, q = i & 15;
                dst[k2*16 + q] = src[k2*64 + (b0 >> 1) + q];
            }
        }
        if (tid < BT) vbuf[tid] = x[(b0 + tid)*T + t];
        __syncthreads();

        // ---- Prefetch projection (embedding gather) — overlaps with GEMM ----
        float proj[4][2];
        #pragma unroll
        for (int bb = 0; bb < 4; ++bb) {
            int vb = vbuf[4*bgrp + bb];
            #pragma unroll
            for (int gg = 0; gg < 2; ++gg) {
                int c = 2*lane + gg;
                int grow = ((c >> 4) << 9) + hu0 + (c & 15);
                proj[bb][gg] = g_WihT[vb*G + grow];
            }
        }

        // ---- GEMM: gates[32b x 64g] += h[32b x 512] @ Wslice^T (packed f32x2 over k) ----
        unsigned long long acc[4][2];
        #pragma unroll
        for (int a = 0; a < 4; ++a) { acc[a][0] = 0ull; acc[a][1] = 0ull; }
        const char* hp = (const char*)(Hs2 + 4*bgrp);   // warp-broadcast reads
        const char* wp = (const char*)(Ws2 + 2*lane);   // contiguous row reads
        #pragma unroll 4
        for (int k2 = 0; k2 < 256; ++k2) {
            ulonglong2 h01 = *(const ulonglong2*)hp;          // (b0,b1) k-pairs
            ulonglong2 h23 = *(const ulonglong2*)(hp + 16);   // (b2,b3)
            ulonglong2 w   = *(const ulonglong2*)wp;          // (g0,g1)
            fma2(acc[0][0], h01.x, w.x); fma2(acc[0][1], h01.x, w.y);
            fma2(acc[1][0], h01.y, w.x); fma2(acc[1][1], h01.y, w.y);
            fma2(acc[2][0], h23.x, w.x); fma2(acc[2][1], h23.x, w.y);
            fma2(acc[3][0], h23.y, w.x); fma2(acc[3][1], h23.y, w.y);
            hp += 32*8; wp += 64*8;
        }

        // ---- Reduce pairs + add proj, stage gates to shared ----
        #pragma unroll
        for (int bb = 0; bb < 4; ++bb) {
            int b = 4*bgrp + bb;
            float2 a0 = u2f(acc[bb][0]);
            float2 a1 = u2f(acc[bb][1]);
            float2 val = make_float2(a0.x + a0.y + proj[bb][0],
                                     a1.x + a1.y + proj[bb][1]);
            *(float2*)&Gs[b*GS_STRIDE + 2*lane] = val;
        }
        __syncthreads();

        // ---- Pointwise LSTM cell (2 h-units per thread, c in registers) ----
        {
            int b = pb;
            int base = b*GS_STRIDE + 2*u2;
            float2 iv = *(float2*)&Gs[base];
            float2 fv = *(float2*)&Gs[base + 16];
            float2 gv = *(float2*)&Gs[base + 32];
            float2 ov = *(float2*)&Gs[base + 48];
            float2 hprev = Hs2[((hu0 >> 1) + u2)*32 + b];

            float ia = sigf(iv.x), ib = sigf(iv.y);
            float fa = sigf(fv.x), fb = sigf(fv.y);
            float ga = tanhf(gv.x), gb = tanhf(gv.y);
            float oa = sigf(ov.x), ob = sigf(ov.y);
            float ca = fa*creg.x + ia*ga;
            float cb = fb*creg.y + ib*gb;
            float ha = oa*tanhf(ca);
            float hb = ob*tanhf(cb);

            bool m = (t < xls[b]);
            float hca = m ? ha : hprev.x;
            float hcb = m ? hb : hprev.y;
            if (m) { creg.x = ca; creg.y = cb; }

            // carried h -> next-step buffer (coalesced 256B per warp)
            g_hbuf[(t + 1) & 1][((hu0 >> 1) + u2)*B + b0 + b] = make_float2(hca, hcb);

            // sequence output
            float2 outv = m ? make_float2(ha, hb) : make_float2(0.f, 0.f);
            size_t obase = ((size_t)(b0 + b)*T + t)*H + hu0 + 2*u2;
            *(float2*)&out[obase] = outv;

            if (t == T - 1) {
                size_t hoff = (size_t)B*T*H + (size_t)(b0 + b)*H + hu0 + 2*u2;
                *(float2*)&out[hoff] = make_float2(hca, hcb);
                *(float2*)&out[hoff + (size_t)B*H] = creg;
            }
        }

        // ---- Grid barrier (all 128 blocks co-resident by construction) ----
        if (t + 1 < T) {
            __syncthreads();
            if (tid == 0) {
                __threadfence();
                atomicAdd(&g_bar, 1u);
                unsigned target = (unsigned)NBLK * (unsigned)(t + 1);
                while (*((volatile unsigned*)&g_bar) < target) { }
                __threadfence();
            }
            __syncthreads();
        }
    }
}

extern "C" void kernel_launch(void* const* d_in, const int* in_sizes, int n_in,
                              void* d_out, int out_size) {
    const int*   x     = (const int*)d_in[0];
    const int*   x_len = (const int*)d_in[1];
    const float* W_ih  = (const float*)d_in[2];
    const float* W_hh  = (const float*)d_in[3];
    const float* b_ih  = (const float*)d_in[4];
    const float* b_hh  = (const float*)d_in[5];
    float* out = (float*)d_out;

    cudaFuncSetAttribute(lstm_persistent,
                         cudaFuncAttributeMaxDynamicSharedMemorySize, SMEM_BYTES);

    init_kernel<<<256, 256>>>(W_ih, b_ih, b_hh);
    lstm_persistent<<<NBLK, NTHR, SMEM_BYTES>>>(x, x_len, W_hh, out);
}

// round 2
// speedup vs baseline: 1.0060x; 1.0060x over previous
#include <cuda_runtime.h>
#include <cstdint>

// Problem constants
#define B   128
#define T   1024
#define H   512
#define G   2048   // 4*H gate columns
#define V   256
#define NBLK 128   // 32 h-unit groups x 4 batch groups
#define NTHR 256
#define BT   32    // batch tile per block
#define GC   64    // gate cols per block (16 h-units x 4 gates)

// Shared memory carve (bytes)
#define WS_BYTES (256*64*8)   // Ws2: [256 k2][64 g] float2   = 131072
#define HS_BYTES (256*32*8)   // Hs2: [256 k2][32 b] float2   =  65536
#define GS_STRIDE 66
#define GS_BYTES (32*GS_STRIDE*4)   // gates staging            =   8448
#define SMEM_BYTES (WS_BYTES + HS_BYTES + GS_BYTES + 128 + 128) // + vbuf + xls = 205312

// Device-global scratch (allocation-free per harness rules)
__device__ float     g_WihT[V*G];              // W_ih^T with biases folded in: [v][g]
__device__ float2    g_hbuf[2][(H/2)*B];       // double-buffered h, k-pair interleaved: [k2][b]
__device__ unsigned  g_bar;

__device__ __forceinline__ void fma2(unsigned long long &d, unsigned long long a, unsigned long long b) {
    asm volatile("fma.rn.f32x2 %0, %1, %2, %0;" : "+l"(d) : "l"(a), "l"(b));
}
__device__ __forceinline__ float2 u2f(unsigned long long v) {
    float2 r; asm("mov.b64 {%0, %1}, %2;" : "=f"(r.x), "=f"(r.y) : "l"(v)); return r;
}
__device__ __forceinline__ float sigf(float x) { return 1.0f / (1.0f + expf(-x)); }

// Per-launch init: reset barrier, zero h0 buffer, build gathered projection table
// projT[v][g] = W_ih[g][v] + b_ih[g] + b_hh[g]
__global__ void init_kernel(const float* __restrict__ W_ih,
                            const float* __restrict__ b_ih,
                            const float* __restrict__ b_hh) {
    int idx = blockIdx.x * blockDim.x + threadIdx.x;
    int stride = gridDim.x * blockDim.x;
    if (idx == 0) g_bar = 0u;
    for (int i = idx; i < V*G; i += stride) {
        int v = i >> 11;           // /G
        int g = i & (G - 1);
        g_WihT[i] = W_ih[g*V + v] + b_ih[g] + b_hh[g];
    }
    for (int i = idx; i < (H/2)*B; i += stride) g_hbuf[0][i] = make_float2(0.f, 0.f);
}

extern __shared__ char smem_raw[];

__global__ __launch_bounds__(NTHR, 1)
void lstm_persistent(const int* __restrict__ x, const int* __restrict__ x_len,
                     const float* __restrict__ W_hh, float* __restrict__ out) {
    float2* Ws2 = (float2*)smem_raw;                       // [256][64] k-pair packed W slice
    float2* Hs2 = (float2*)(smem_raw + WS_BYTES);          // [256][32] k-pair packed h tile
    float*  Gs  = (float*)(smem_raw + WS_BYTES + HS_BYTES);// [32][66] gates
    int*   vbuf = (int*)(Gs + 32*GS_STRIDE);               // [32] token ids this step
    int*   xls  = vbuf + 32;                               // [32] x_len cache

    const int tid  = threadIdx.x;
    const int hug  = blockIdx.x & 31;   // h-unit group
    const int bg   = blockIdx.x >> 5;   // batch group
    const int hu0  = hug * 16;
    const int b0   = bg * BT;
    const int lane = tid & 31;          // gate-col group (2 cols each)
    const int bgrp = tid >> 5;          // batch group within tile (4 rows each)

    // ---- Prologue: load W_hh slice (resident all 1024 steps), x_len cache ----
    for (int i = tid; i < GC*256; i += NTHR) {
        int k2 = i >> 6, c = i & 63;
        int grow = ((c >> 4) << 9) + hu0 + (c & 15);   // gate_type*512 + hu0 + u
        Ws2[k2*64 + c] = *(const float2*)&W_hh[grow*H + 2*k2];
    }
    if (tid < BT) xls[tid] = x_len[b0 + tid];

    // Pointwise mapping (fixed per thread for the whole kernel -> c lives in regs)
    const int u2 = tid >> 5;   // 0..7  (h-unit pair index)
    const int pb = tid & 31;   // batch row
    float2 creg = make_float2(0.f, 0.f);

    for (int t = 0; t < T; ++t) {
        // ---- Fill Hs2 from global h (double-buffered) ----
        {
            const float4* src = (const float4*)(g_hbuf[t & 1]);
            float4* dst = (float4*)Hs2;
            #pragma unroll
            for (int i = tid; i < 4096; i += NTHR) {
                int k2 = i >> 4, q = i & 15;
                dst[k2*16 + q] = src[k2*64 + (b0 >> 1) + q];
            }
        }
        if (tid < BT) vbuf[tid] = x[(b0 + tid)*T + t];
        __syncthreads();

        // ---- Prefetch projection (embedding gather) — overlaps with GEMM ----
        float proj[4][2];
        #pragma unroll
        for (int bb = 0; bb < 4; ++bb) {
            int vb = vbuf[4*bgrp + bb];
            #pragma unroll
            for (int gg = 0; gg < 2; ++gg) {
                int c = 2*lane + gg;
                int grow = ((c >> 4) << 9) + hu0 + (c & 15);
                proj[bb][gg] = g_WihT[vb*G + grow];
            }
        }

        // ---- GEMM: gates[32b x 64g] += h[32b x 512] @ Wslice^T (packed f32x2 over k) ----
        unsigned long long acc[4][2];
        #pragma unroll
        for (int a = 0; a < 4; ++a) { acc[a][0] = 0ull; acc[a][1] = 0ull; }
        const char* hp = (const char*)(Hs2 + 4*bgrp);   // warp-broadcast reads
        const char* wp = (const char*)(Ws2 + 2*lane);   // contiguous row reads
        #pragma unroll 4
        for (int k2 = 0; k2 < 256; ++k2) {
            ulonglong2 h01 = *(const ulonglong2*)hp;          // (b0,b1) k-pairs
            ulonglong2 h23 = *(const ulonglong2*)(hp + 16);   // (b2,b3)
            ulonglong2 w   = *(const ulonglong2*)wp;          // (g0,g1)
            fma2(acc[0][0], h01.x, w.x); fma2(acc[0][1], h01.x, w.y);
            fma2(acc[1][0], h01.y, w.x); fma2(acc[1][1], h01.y, w.y);
            fma2(acc[2][0], h23.x, w.x); fma2(acc[2][1], h23.x, w.y);
            fma2(acc[3][0], h23.y, w.x); fma2(acc[3][1], h23.y, w.y);
            hp += 32*8; wp += 64*8;
        }

        // ---- Reduce pairs + add proj, stage gates to shared ----
        #pragma unroll
        for (int bb = 0; bb < 4; ++bb) {
            int b = 4*bgrp + bb;
            float2 a0 = u2f(acc[bb][0]);
            float2 a1 = u2f(acc[bb][1]);
            float2 val = make_float2(a0.x + a0.y + proj[bb][0],
                                     a1.x + a1.y + proj[bb][1]);
            *(float2*)&Gs[b*GS_STRIDE + 2*lane] = val;
        }
        __syncthreads();

        // ---- Pointwise LSTM cell (2 h-units per thread, c in registers) ----
        {
            int b = pb;
            int base = b*GS_STRIDE + 2*u2;
            float2 iv = *(float2*)&Gs[base];
            float2 fv = *(float2*)&Gs[base + 16];
            float2 gv = *(float2*)&Gs[base + 32];
            float2 ov = *(float2*)&Gs[base + 48];
            float2 hprev = Hs2[((hu0 >> 1) + u2)*32 + b];

            float ia = sigf(iv.x), ib = sigf(iv.y);
            float fa = sigf(fv.x), fb = sigf(fv.y);
            float ga = tanhf(gv.x), gb = tanhf(gv.y);
            float oa = sigf(ov.x), ob = sigf(ov.y);
            float ca = fa*creg.x + ia*ga;
            float cb = fb*creg.y + ib*gb;
            float ha = oa*tanhf(ca);
            float hb = ob*tanhf(cb);

            bool m = (t < xls[b]);
            float hca = m ? ha : hprev.x;
            float hcb = m ? hb : hprev.y;
            if (m) { creg.x = ca; creg.y = cb; }

            // carried h -> next-step buffer (coalesced 256B per warp)
            g_hbuf[(t + 1) & 1][((hu0 >> 1) + u2)*B + b0 + b] = make_float2(hca, hcb);

            // sequence output
            float2 outv = m ? make_float2(ha, hb) : make_float2(0.f, 0.f);
            size_t obase = ((size_t)(b0 + b)*T + t)*H + hu0 + 2*u2;
            *(float2*)&out[obase] = outv;

            if (t == T - 1) {
                size_t hoff = (size_t)B*T*H + (size_t)(b0 + b)*H + hu0 + 2*u2;
                *(float2*)&out[hoff] = make_float2(hca, hcb);
                *(float2*)&out[hoff + (size_t)B*H] = creg;
            }
        }

        // ---- Grid barrier (all 128 blocks co-resident by construction) ----
        if (t + 1 < T) {
            __syncthreads();
            if (tid == 0) {
                __threadfence();
                atomicAdd(&g_bar, 1u);
                unsigned target = (unsigned)NBLK * (unsigned)(t + 1);
                while (*((volatile unsigned*)&g_bar) < target) { }
                __threadfence();
            }
            __syncthreads();
        }
    }
}

extern "C" void kernel_launch(void* const* d_in, const int* in_sizes, int n_in,
                              void* d_out, int out_size) {
    const int*   x     = (const int*)d_in[0];
    const int*   x_len = (const int*)d_in[1];
    const float* W_ih  = (const float*)d_in[2];
    const float* W_hh  = (const float*)d_in[3];
    const float* b_ih  = (const float*)d_in[4];
    const float* b_hh  = (const float*)d_in[5];
    float* out = (float*)d_out;

    cudaFuncSetAttribute(lstm_persistent,
                         cudaFuncAttributeMaxDynamicSharedMemorySize, SMEM_BYTES);

    init_kernel<<<256, 256>>>(W_ih, b_ih, b_hh);
    lstm_persistent<<<NBLK, NTHR, SMEM_BYTES>>>(x, x_len, W_hh, out);
}